// round 9
// baseline (speedup 1.0000x reference)
#include <cuda_runtime.h>
#include <stdint.h>

// ScaledNeuron: IF neuron, soft reset, V_TH=1.0, SCALE=1.0, v0=0.5.
// xs: [B=16, C=64, H=64, W=64, T=8] fp32, T contiguous.
//
// Perfect coalescing (one float4 = half a location per lane; temporal
// recurrence stitched across the even/odd lane pair with shfl_up) with
// MLP=4: each thread handles float4s i, i+q, i+2q, i+3q (q = n4/4), all
// four loads front-batched. Each stream is lane-consecutive (16B/lane),
// and q is even so lane parity == element parity for all streams.

__device__ __forceinline__ float4 if4(float4 x, float& v) {
    float s0, s1, s2, s3;
    v += x.x; s0 = (v >= 1.0f) ? 1.0f : 0.0f; v -= s0;
    v += x.y; s1 = (v >= 1.0f) ? 1.0f : 0.0f; v -= s1;
    v += x.z; s2 = (v >= 1.0f) ? 1.0f : 0.0f; v -= s2;
    v += x.w; s3 = (v >= 1.0f) ? 1.0f : 0.0f; v -= s3;
    return make_float4(s0, s1, s2, s3);
}

__global__ __launch_bounds__(256)
void scaled_neuron_kernel(const float4* __restrict__ in,
                          float4* __restrict__ out,
                          int quarter) {        // quarter = n4 / 4
    int i = blockIdx.x * blockDim.x + threadIdx.x;
    if (i >= quarter) return;

    // Front-batched, all perfectly coalesced (MLP_p1 = 4).
    float4 x0 = in[i];
    float4 x1 = in[i + quarter];
    float4 x2 = in[i + 2 * quarter];
    float4 x3 = in[i + 3 * quarter];

    // Pass 1 (valid for even lanes: t0..3 of each location).
    float v0 = 0.5f, v1 = 0.5f, v2 = 0.5f, v3 = 0.5f;
    float4 s0 = if4(x0, v0);
    float4 s1 = if4(x1, v1);
    float4 s2 = if4(x2, v2);
    float4 s3 = if4(x3, v3);

    // Even lane hands its v-after-t3 to its odd partner.
    float p0 = __shfl_up_sync(0xffffffffu, v0, 1);
    float p1 = __shfl_up_sync(0xffffffffu, v1, 1);
    float p2 = __shfl_up_sync(0xffffffffu, v2, 1);
    float p3 = __shfl_up_sync(0xffffffffu, v3, 1);

    if (threadIdx.x & 1) {
        float w0 = p0, w1 = p1, w2 = p2, w3 = p3;
        s0 = if4(x0, w0);   // Pass 2: t4..7 from partner's v.
        s1 = if4(x1, w1);
        s2 = if4(x2, w2);
        s3 = if4(x3, w3);
    }

    out[i]               = s0;
    out[i + quarter]     = s1;
    out[i + 2 * quarter] = s2;
    out[i + 3 * quarter] = s3;
}

extern "C" void kernel_launch(void* const* d_in, const int* in_sizes, int n_in,
                              void* d_out, int out_size) {
    const float4* in = (const float4*)d_in[0];
    float4* out = (float4*)d_out;

    int n4 = in_sizes[0] / 4;    // 8,388,608 float4
    int quarter = n4 / 4;        // 2,097,152 (even)
    int threads = 256;
    int blocks = (quarter + threads - 1) / threads;  // 8192

    scaled_neuron_kernel<<<blocks, threads>>>(in, out, quarter);
}